// round 13
// baseline (speedup 1.0000x reference)
#include <cuda_runtime.h>
#include <cuda_bf16.h>
#include <math.h>
#include <stdint.h>

#define BB 64
#define TT 256
#define EE 300
#define UU 512
#define GG 2048
#define TBT (BB*TT)     /* 16384 rows per direction */

// ---------------- device scratch (static allocation only) ----------------
__device__ float g_hall1[(size_t)2 * TBT * UU];   // [2][B][T][U]  final-layer h (fp32)
__device__ float g_enc[(size_t)TBT * UU];         // [B][T][U]
__device__ float g_scores[TBT];                   // [B][T]
__device__ float g_pooled[BB * UU];               // [B][U]
__device__ int g_flagF[(TT + 2) * 128];           // [iter][dir*64+slice]
// full-T bf16 A-fragment rings: [dir][t][mt][4096] u32
__device__ uint32_t g_ring1[(size_t)2 * TT * 4 * 4096];   // h1 (layer0 out)
__device__ uint32_t g_ring2[(size_t)2 * TT * 4 * 4096];   // h2 (layer1 out)
__device__ uint32_t g_ring3[(size_t)2 * TT * 4 * 4096];   // h3 (layer2 out)

__device__ __forceinline__ float sigf(float x) { return 1.f / (1.f + __expf(-x)); }
__device__ __forceinline__ float ssf(float x)  { return x / (1.f + fabsf(x)); }

__device__ __forceinline__ void stRel(int* p) {
    asm volatile("st.release.gpu.global.s32 [%0], %1;" :: "l"(p), "r"(1) : "memory");
}
__device__ __forceinline__ int acqLd(const int* p) {
    int v; asm volatile("ld.acquire.gpu.global.s32 %0, [%1];" : "=r"(v) : "l"(p) : "memory");
    return v;
}

#define MMA_BF16(d0,d1,d2,d3,a0,a1,a2,a3,b0,b1) \
    asm volatile("mma.sync.aligned.m16n8k16.row.col.f32.bf16.bf16.f32 " \
        "{%0,%1,%2,%3}, {%4,%5,%6,%7}, {%8,%9}, {%0,%1,%2,%3};" \
        : "+f"(d0), "+f"(d1), "+f"(d2), "+f"(d3) \
        : "r"(a0), "r"(a1), "r"(a2), "r"(a3), "r"(b0), "r"(b1))

// ---- stage a 512x32-gate-col weight slice as bf16 B-fragments ----
__device__ __forceinline__ void stage_wfrags32(
    uint32_t* dstW, const float* W, int u0, int tid, int nthr)
{
    for (int i = tid; i < 32 * 4 * 32; i += nthr) {
        int cc = i >> 7;
        int nt = (i >> 5) & 3;
        int lane = i & 31;
        int gq = lane >> 2, t4 = lane & 3;
        int col = nt * 8 + gq;                 // gate = col>>3, unit = col&7
        long wcol = (long)(col >> 3) * UU + u0 + (col & 7);
        int k0 = cc * 16 + 2 * t4;
        __nv_bfloat162 b0, b1;
        b0.x = __float2bfloat16_rn(W[(long)k0 * GG + wcol]);
        b0.y = __float2bfloat16_rn(W[(long)(k0 + 1) * GG + wcol]);
        b1.x = __float2bfloat16_rn(W[(long)(k0 + 8) * GG + wcol]);
        b1.y = __float2bfloat16_rn(W[(long)(k0 + 9) * GG + wcol]);
        uint32_t* dst = dstW + (((cc * 2 + (nt >> 1)) * 32 + lane) << 2) + (nt & 1) * 2;
        dst[0] = *(uint32_t*)&b0;
        dst[1] = *(uint32_t*)&b1;
    }
}

// ---- stage the k0 (input-proj) slice: K=300, 19 chunks, zero-padded tail ----
__device__ __forceinline__ void stage_wfrags_k0(
    uint32_t* dstW, const float* W, int u0, int tid, int nthr)
{
    for (int i = tid; i < 19 * 4 * 32; i += nthr) {
        int cc = i >> 7;
        int nt = (i >> 5) & 3;
        int lane = i & 31;
        int gq = lane >> 2, t4 = lane & 3;
        int col = nt * 8 + gq;
        long wcol = (long)(col >> 3) * UU + u0 + (col & 7);
        int k0 = cc * 16 + 2 * t4;
        __nv_bfloat16 z = __float2bfloat16_rn(0.f);
        __nv_bfloat162 b0, b1;
        b0.x = (k0     < EE) ? __float2bfloat16_rn(W[(long)k0 * GG + wcol])       : z;
        b0.y = (k0 + 1 < EE) ? __float2bfloat16_rn(W[(long)(k0 + 1) * GG + wcol]) : z;
        b1.x = (k0 + 8 < EE) ? __float2bfloat16_rn(W[(long)(k0 + 8) * GG + wcol]) : z;
        b1.y = (k0 + 9 < EE) ? __float2bfloat16_rn(W[(long)(k0 + 9) * GG + wcol]) : z;
        uint32_t* dst = dstW + (((cc * 2 + (nt >> 1)) * 32 + lane) << 2) + (nt & 1) * 2;
        dst[0] = *(uint32_t*)&b0;
        dst[1] = *(uint32_t*)&b1;
    }
}

// ---- single bf16 mma stream, full 32 cols per warp ----
__device__ __forceinline__ void mma_stream4(
    float acc[4][4], const uint32_t* ring, const uint32_t* Ws, int lane)
{
    const uint4* r = (const uint4*)ring;
    uint4 buf[8];
    #pragma unroll
    for (int i = 0; i < 8; i++) buf[i] = r[i * 32 + lane];
    #pragma unroll
    for (int cc = 0; cc < 32; cc++) {
        uint4 av = buf[cc & 7];
        if (cc + 8 < 32) buf[cc & 7] = r[(cc + 8) * 32 + lane];
        uint4 b0 = *(const uint4*)&Ws[((cc * 2 + 0) * 32 + lane) << 2];
        uint4 b1 = *(const uint4*)&Ws[((cc * 2 + 1) * 32 + lane) << 2];
        MMA_BF16(acc[0][0], acc[0][1], acc[0][2], acc[0][3],
                 av.x, av.y, av.z, av.w, b0.x, b0.y);
        MMA_BF16(acc[1][0], acc[1][1], acc[1][2], acc[1][3],
                 av.x, av.y, av.z, av.w, b0.z, b0.w);
        MMA_BF16(acc[2][0], acc[2][1], acc[2][2], acc[2][3],
                 av.x, av.y, av.z, av.w, b1.x, b1.y);
        MMA_BF16(acc[3][0], acc[3][1], acc[3][2], acc[3][3],
                 av.x, av.y, av.z, av.w, b1.z, b1.w);
    }
}

// ---- dual interleaved streams ----
__device__ __forceinline__ void mma_dual(
    float acc[4][4],
    const uint32_t* ringA, const uint32_t* WsA,
    const uint32_t* ringB, const uint32_t* WsB, int lane)
{
    const uint4* rA = (const uint4*)ringA;
    const uint4* rB = (const uint4*)ringB;
    uint4 bufA[4], bufB[4];
    #pragma unroll
    for (int i = 0; i < 4; i++) { bufA[i] = rA[i * 32 + lane];
                                  bufB[i] = rB[i * 32 + lane]; }
    #pragma unroll
    for (int cc = 0; cc < 32; cc++) {
        uint4 av = bufA[cc & 3];
        uint4 bv = bufB[cc & 3];
        if (cc + 4 < 32) { bufA[cc & 3] = rA[(cc + 4) * 32 + lane];
                           bufB[cc & 3] = rB[(cc + 4) * 32 + lane]; }
        uint4 a0 = *(const uint4*)&WsA[((cc * 2 + 0) * 32 + lane) << 2];
        uint4 a1 = *(const uint4*)&WsA[((cc * 2 + 1) * 32 + lane) << 2];
        MMA_BF16(acc[0][0], acc[0][1], acc[0][2], acc[0][3],
                 av.x, av.y, av.z, av.w, a0.x, a0.y);
        MMA_BF16(acc[1][0], acc[1][1], acc[1][2], acc[1][3],
                 av.x, av.y, av.z, av.w, a0.z, a0.w);
        MMA_BF16(acc[2][0], acc[2][1], acc[2][2], acc[2][3],
                 av.x, av.y, av.z, av.w, a1.x, a1.y);
        MMA_BF16(acc[3][0], acc[3][1], acc[3][2], acc[3][3],
                 av.x, av.y, av.z, av.w, a1.z, a1.w);
        uint4 b0 = *(const uint4*)&WsB[((cc * 2 + 0) * 32 + lane) << 2];
        uint4 b1 = *(const uint4*)&WsB[((cc * 2 + 1) * 32 + lane) << 2];
        MMA_BF16(acc[0][0], acc[0][1], acc[0][2], acc[0][3],
                 bv.x, bv.y, bv.z, bv.w, b0.x, b0.y);
        MMA_BF16(acc[1][0], acc[1][1], acc[1][2], acc[1][3],
                 bv.x, bv.y, bv.z, bv.w, b0.z, b0.w);
        MMA_BF16(acc[2][0], acc[2][1], acc[2][2], acc[2][3],
                 bv.x, bv.y, bv.z, bv.w, b1.x, b1.y);
        MMA_BF16(acc[3][0], acc[3][1], acc[3][2], acc[3][3],
                 bv.x, bv.y, bv.z, bv.w, b1.z, b1.w);
    }
}

// ====== fused: input GEMM (warp group 3) + 3-layer bidir LSTM wavefront =========
// 128 blocks: d = bx>>6, slice = bx&63 -> 8 units (32 gate cols), all layers.
// 512 threads = 16 warps: sg 0..2 = LSTM stages (4 warps each), sg 3 = z producer.
// Producer computes z[t=i+3] = emb[ids[:,t]] @ k0slice + bias0 into 4-slot SMEM ring.
#define ZRING_F 2304                 /* floats per slot: 64 rows x 36 (stride) */
#define FUSED_SMEM_BYTES (163840 + 19456 + 4*ZRING_F*4)

__global__ __launch_bounds__(512) void fused_lstm(
    const int* __restrict__ ids, const float* __restrict__ emb,
    const float* __restrict__ k0Base,
    const float* __restrict__ recBase, const float* __restrict__ k12Base,
    const float* __restrict__ biasBase)
{
    extern __shared__ char smraw[];
    uint32_t* Ws0  = (uint32_t*)smraw;         // rec layer0
    uint32_t* Ws1k = Ws0 + 8192;               // k12 layer1
    uint32_t* Ws1r = Ws0 + 16384;              // rec layer1
    uint32_t* Ws2k = Ws0 + 24576;              // k12 layer2
    uint32_t* Ws2r = Ws0 + 32768;              // rec layer2
    uint32_t* Wk0  = Ws0 + 40960;              // k0 input proj (19 chunks, 4864 u32)
    float*    zS   = (float*)(smraw + 163840 + 19456);   // [4][64][36]

    const int bx = blockIdx.x;
    const int d     = bx >> 6;
    const int slice = bx & 63;
    const int u0    = slice * 8;
    const int tid = threadIdx.x;

    stage_wfrags32(Ws0,  recBase + ((long)d * 3 + 0) * UU * GG, u0, tid, 512);
    stage_wfrags32(Ws1k, k12Base + ((long)d * 2 + 0) * UU * GG, u0, tid, 512);
    stage_wfrags32(Ws1r, recBase + ((long)d * 3 + 1) * UU * GG, u0, tid, 512);
    stage_wfrags32(Ws2k, k12Base + ((long)d * 2 + 1) * UU * GG, u0, tid, 512);
    stage_wfrags32(Ws2r, recBase + ((long)d * 3 + 2) * UU * GG, u0, tid, 512);
    stage_wfrags_k0(Wk0, k0Base + (long)d * EE * GG, u0, tid, 512);
    __syncthreads();

    const int lane = tid & 31;
    const int wid  = tid >> 5;
    const int sg   = wid >> 2;        // 0..2 = stages, 3 = z producer
    const int wi   = wid & 3;         // m-tile within group
    const int g    = lane >> 2;
    const int t4   = lane & 3;

    const int R = wi * 16 + g;        // first owned batch row (second is R+8)
    const int ringSlot = (((slice >> 1) * 32 + lane) << 2) + 2 * (slice & 1);

    // bias regs: stages 1,2 use bias in epilogue; producer folds bias0 into z
    float2 bg2[4];
    {
        int lsel = (sg == 3) ? 0 : sg;
        const float* bp = biasBase + ((long)d * 3 + lsel) * GG;
        #pragma unroll
        for (int q = 0; q < 4; q++)
            bg2[q] = *(const float2*)&bp[q * UU + u0 + 2 * t4];
    }

    uint32_t* ringOut = (sg == 0) ? g_ring1 : ((sg == 1) ? g_ring2 : g_ring3);

    // ---- z producer routine: z[t] -> zS[slot] ----
    auto gemm_z = [&](int t, int slot) {
        int tt = d ? (TT - 1 - t) : t;
        const float* e0 = emb + (long)ids[R * TT + tt] * EE;
        const float* e1 = emb + (long)ids[(R + 8) * TT + tt] * EE;
        float acc[4][4];
        #pragma unroll
        for (int q = 0; q < 4; q++)
            #pragma unroll
            for (int r = 0; r < 4; r++) acc[q][r] = 0.f;

        #pragma unroll 4
        for (int cc = 0; cc < 19; cc++) {
            int kb = cc * 16 + 2 * t4;
            uint32_t a0, a1, a2, a3;
            {
                float2 v = *(const float2*)&e0[kb];
                __nv_bfloat162 p; p.x = __float2bfloat16_rn(v.x); p.y = __float2bfloat16_rn(v.y);
                a0 = *(uint32_t*)&p;
            }
            {
                float2 v = *(const float2*)&e1[kb];
                __nv_bfloat162 p; p.x = __float2bfloat16_rn(v.x); p.y = __float2bfloat16_rn(v.y);
                a1 = *(uint32_t*)&p;
            }
            if (kb + 8 < EE) {
                float2 v = *(const float2*)&e0[kb + 8];
                __nv_bfloat162 p; p.x = __float2bfloat16_rn(v.x); p.y = __float2bfloat16_rn(v.y);
                a2 = *(uint32_t*)&p;
                float2 w = *(const float2*)&e1[kb + 8];
                __nv_bfloat162 q2; q2.x = __float2bfloat16_rn(w.x); q2.y = __float2bfloat16_rn(w.y);
                a3 = *(uint32_t*)&q2;
            } else { a2 = 0; a3 = 0; }

            uint4 b0 = *(const uint4*)&Wk0[((cc * 2 + 0) * 32 + lane) << 2];
            uint4 b1 = *(const uint4*)&Wk0[((cc * 2 + 1) * 32 + lane) << 2];
            MMA_BF16(acc[0][0], acc[0][1], acc[0][2], acc[0][3],
                     a0, a1, a2, a3, b0.x, b0.y);
            MMA_BF16(acc[1][0], acc[1][1], acc[1][2], acc[1][3],
                     a0, a1, a2, a3, b0.z, b0.w);
            MMA_BF16(acc[2][0], acc[2][1], acc[2][2], acc[2][3],
                     a0, a1, a2, a3, b1.x, b1.y);
            MMA_BF16(acc[3][0], acc[3][1], acc[3][2], acc[3][3],
                     a0, a1, a2, a3, b1.z, b1.w);
        }
        float* zw = &zS[slot * ZRING_F + R * 36 + 2 * t4];
        #pragma unroll
        for (int q = 0; q < 4; q++) {
            *(float2*)&zw[q * 8] =
                make_float2(acc[q][0] + bg2[q].x, acc[q][1] + bg2[q].y);
            *(float2*)&zw[8 * 36 + q * 8] =
                make_float2(acc[q][2] + bg2[q].x, acc[q][3] + bg2[q].y);
        }
    };

    // ---- prologue: fill z slots for t = 0..2 ----
    if (sg == 3) {
        for (int p = 0; p < 3; p++) gemm_z(p, p);
    }
    __syncthreads();

    float4 cell = make_float4(0.f, 0.f, 0.f, 0.f);

    for (int i = 0; i < TT + 2; i++) {
        const bool s0 = (i < TT);
        const bool s1 = (i >= 1 && i <= TT);
        const bool s2 = (i >= 2);
        const int t0 = i, t1 = i - 1, t2 = i - 2;
        const bool act = (sg == 0) ? s0 : ((sg == 1) ? s1 : (sg == 2 ? s2 : false));
        const int ts = (sg == 0) ? t0 : ((sg == 1) ? t1 : t2);

        // ---- single wait: all same-dir blocks' iteration i-1 flags ----
        if (i > 0) {
            if (tid < 64) {
                const int* p = &g_flagF[(i - 1) * 128 + d * 64 + tid];
                while (acqLd(p) == 0) { }
            }
            __syncthreads();
        }

        // ---- per-group work ----
        float acc[4][4];
        #pragma unroll
        for (int q = 0; q < 4; q++)
            #pragma unroll
            for (int r = 0; r < 4; r++) acc[q][r] = 0.f;

        if (sg == 0) {
            if (s0 && t0 > 0)
                mma_stream4(acc, &g_ring1[((size_t)(d * TT + t0 - 1) * 4 + wi) * 4096],
                            Ws0, lane);
        } else if (sg == 1) {
            if (s1) {
                if (t1 > 0)
                    mma_dual(acc, &g_ring1[((size_t)(d * TT + t1) * 4 + wi) * 4096], Ws1k,
                             &g_ring2[((size_t)(d * TT + t1 - 1) * 4 + wi) * 4096], Ws1r,
                             lane);
                else
                    mma_stream4(acc, &g_ring1[((size_t)(d * TT + t1) * 4 + wi) * 4096],
                                Ws1k, lane);
            }
        } else if (sg == 2) {
            if (s2) {
                if (t2 > 0)
                    mma_dual(acc, &g_ring2[((size_t)(d * TT + t2) * 4 + wi) * 4096], Ws2k,
                             &g_ring3[((size_t)(d * TT + t2 - 1) * 4 + wi) * 4096], Ws2r,
                             lane);
                else
                    mma_stream4(acc, &g_ring2[((size_t)(d * TT + t2) * 4 + wi) * 4096],
                                Ws2k, lane);
            }
        } else {
            // z producer: compute z[t=i+3] into slot (i+3)&3
            if (i + 3 < TT) gemm_z(i + 3, (i + 3) & 3);
        }

        // ---- register epilogue (stages only) ----
        if (act) {
            float2 aA[4], aB[4];
            if (sg == 0) {
                const float* zr = &zS[(i & 3) * ZRING_F + R * 36 + 2 * t4];
                #pragma unroll
                for (int q = 0; q < 4; q++) {
                    aA[q] = *(const float2*)&zr[q * 8];
                    aB[q] = *(const float2*)&zr[8 * 36 + q * 8];
                }
            } else {
                #pragma unroll
                for (int q = 0; q < 4; q++) { aA[q] = bg2[q]; aB[q] = bg2[q]; }
            }
            float ci0 = acc[0][0] + aA[0].x, ci1 = acc[0][1] + aA[0].y;
            float cf0 = acc[1][0] + aA[1].x, cf1 = acc[1][1] + aA[1].y;
            float cg0 = acc[2][0] + aA[2].x, cg1 = acc[2][1] + aA[2].y;
            float co0 = acc[3][0] + aA[3].x, co1 = acc[3][1] + aA[3].y;
            float ci2 = acc[0][2] + aB[0].x, ci3 = acc[0][3] + aB[0].y;
            float cf2 = acc[1][2] + aB[1].x, cf3 = acc[1][3] + aB[1].y;
            float cg2v = acc[2][2] + aB[2].x, cg3 = acc[2][3] + aB[2].y;
            float co2 = acc[3][2] + aB[3].x, co3 = acc[3][3] + aB[3].y;

            cell.x = sigf(cf0) * cell.x + sigf(ci0) * ssf(cg0);
            cell.y = sigf(cf1) * cell.y + sigf(ci1) * ssf(cg1);
            cell.z = sigf(cf2) * cell.z + sigf(ci2) * ssf(cg2v);
            cell.w = sigf(cf3) * cell.w + sigf(ci3) * ssf(cg3);
            float h0 = sigf(co0) * ssf(cell.x);
            float h1 = sigf(co1) * ssf(cell.y);
            float h2 = sigf(co2) * ssf(cell.z);
            float h3 = sigf(co3) * ssf(cell.w);

            if (sg == 2) {
                long hb = ((long)d * TBT + (long)R * TT + ts) * UU + u0 + 2 * t4;
                *(float2*)&g_hall1[hb] = make_float2(h0, h1);
                *(float2*)&g_hall1[hb + (long)8 * TT * UU] = make_float2(h2, h3);
            }
            __nv_bfloat162 p0, p1;
            p0.x = __float2bfloat16_rn(h0); p0.y = __float2bfloat16_rn(h1);
            p1.x = __float2bfloat16_rn(h2); p1.y = __float2bfloat16_rn(h3);
            uint2 pk = make_uint2(*(uint32_t*)&p0, *(uint32_t*)&p1);
            *(uint2*)&ringOut[((size_t)(d * TT + ts) * 4 + wi) * 4096 + ringSlot] = pk;
        }

        // ---- signal this block's iteration-i products ----
        __syncthreads();
        if (tid == 0) stRel(&g_flagF[i * 128 + d * 64 + slice]);
    }
}

__global__ void zero_flags() {
    int i = blockIdx.x * 256 + threadIdx.x;
    if (i < (TT + 2) * 128) g_flagF[i] = 0;
}

__global__ void enc_avg() {
    size_t i = (size_t)blockIdx.x * blockDim.x + threadIdx.x;
    if (i < (size_t)TBT * UU)
        g_enc[i] = 0.5f * (g_hall1[i] + g_hall1[(size_t)TBT * UU + i]);
}

// ---------------- attention scores ----------------
__global__ __launch_bounds__(256) void att_scores(
    const float* __restrict__ Wa0, const float* __restrict__ ba0,
    const float* __restrict__ alpha_a, const float* __restrict__ Wa1,
    const float* __restrict__ ba1)
{
    const int b = blockIdx.x;
    const int t0 = blockIdx.y * 16;
    __shared__ float encsT[512][16];
    __shared__ float red[256];
    const int tid = threadIdx.x;

    for (int i = tid; i < 16 * 512; i += 256) {
        int tt = i >> 9, u = i & 511;
        encsT[u][tt] = g_enc[((size_t)b * TT + t0 + tt) * UU + u];
    }
    __syncthreads();

    float a[16];
    float bb = ba0[tid];
    #pragma unroll
    for (int q = 0; q < 16; q++) a[q] = bb;

    for (int u = 0; u < 512; u++) {
        float w = Wa0[u * 256 + tid];
        const float4* row = (const float4*)encsT[u];
        float4 e0 = row[0], e1 = row[1], e2 = row[2], e3 = row[3];
        a[0]  += e0.x * w; a[1]  += e0.y * w; a[2]  += e0.z * w; a[3]  += e0.w * w;
        a[4]  += e1.x * w; a[5]  += e1.y * w; a[6]  += e1.z * w; a[7]  += e1.w * w;
        a[8]  += e2.x * w; a[9]  += e2.y * w; a[10] += e2.z * w; a[11] += e2.w * w;
        a[12] += e3.x * w; a[13] += e3.y * w; a[14] += e3.z * w; a[15] += e3.w * w;
    }

    float al = alpha_a[tid], w1 = Wa1[tid], b1v = ba1[0];
    for (int q = 0; q < 16; q++) {
        float v = a[q];
        v = (v >= 0.f) ? v : al * v;
        v *= w1;
        red[tid] = v; __syncthreads();
        for (int s = 128; s > 0; s >>= 1) {
            if (tid < s) red[tid] += red[tid + s];
            __syncthreads();
        }
        if (tid == 0) g_scores[b * TT + t0 + q] = red[0] + b1v;
        __syncthreads();
    }
}

// ---------------- softmax over T + weighted pooling ----------------
__global__ __launch_bounds__(256) void softmax_pool() {
    const int b = blockIdx.x;
    const int tid = threadIdx.x;
    __shared__ float ws[256];
    __shared__ float red[256];

    float s = g_scores[b * TT + tid];
    red[tid] = s; __syncthreads();
    for (int st = 128; st > 0; st >>= 1) {
        if (tid < st) red[tid] = fmaxf(red[tid], red[tid + st]);
        __syncthreads();
    }
    float mx = red[0]; __syncthreads();
    float e = expf(s - mx);
    red[tid] = e; __syncthreads();
    for (int st = 128; st > 0; st >>= 1) {
        if (tid < st) red[tid] += red[tid + st];
        __syncthreads();
    }
    float sum = red[0]; __syncthreads();
    ws[tid] = e / sum;
    __syncthreads();

    for (int u = tid; u < UU; u += 256) {
        float acc = 0.f;
        for (int t = 0; t < TT; t++)
            acc += g_enc[((size_t)b * TT + t) * UU + u] * ws[t];
        g_pooled[b * UU + u] = acc;
    }
}

// ---------------- classification head ----------------
__global__ __launch_bounds__(256) void head(
    const float* __restrict__ Wd0, const float* __restrict__ bd0,
    const float* __restrict__ gamma, const float* __restrict__ beta,
    const float* __restrict__ bnm, const float* __restrict__ bnv,
    const float* __restrict__ alpha_h, const float* __restrict__ Wd1,
    const float* __restrict__ bd1, float* __restrict__ out)
{
    const int b = blockIdx.x, j = threadIdx.x;
    __shared__ float ps[512];
    __shared__ float hs[256];
    __shared__ float lgs[7];

    for (int u = j; u < 512; u += 256) ps[u] = g_pooled[b * UU + u];
    __syncthreads();

    float h = bd0[j];
    for (int u = 0; u < 512; u++) h += ps[u] * Wd0[u * 256 + j];
    h = (h - bnm[j]) * rsqrtf(bnv[j] + 1e-3f) * gamma[j] + beta[j];
    h = (h >= 0.f) ? h : alpha_h[j] * h;
    hs[j] = h;
    __syncthreads();

    if (j < 7) {
        float lg = bd1[j];
        for (int k = 0; k < 256; k++) lg += hs[k] * Wd1[k * 7 + j];
        lgs[j] = lg;
    }
    __syncthreads();
    if (j == 0) {
        float mx = lgs[0];
        for (int l = 1; l < 7; l++) mx = fmaxf(mx, lgs[l]);
        float sum = 0.f, e[7];
        for (int l = 0; l < 7; l++) { e[l] = expf(lgs[l] - mx); sum += e[l]; }
        for (int l = 0; l < 7; l++) out[b * 7 + l] = e[l] / sum;
    }
}

// ---------------- driver ----------------
extern "C" void kernel_launch(void* const* d_in, const int* in_sizes, int n_in,
                              void* d_out, int out_size)
{
    const int*   ids   = (const int*)  d_in[0];
    const float* emb   = (const float*)d_in[1];
    const float* k0    = (const float*)d_in[2];
    const float* k12   = (const float*)d_in[3];
    const float* rec   = (const float*)d_in[4];
    const float* bias  = (const float*)d_in[5];
    const float* Wa0   = (const float*)d_in[6];
    const float* ba0   = (const float*)d_in[7];
    const float* al_a  = (const float*)d_in[8];
    const float* Wa1   = (const float*)d_in[9];
    const float* ba1   = (const float*)d_in[10];
    const float* Wd0   = (const float*)d_in[11];
    const float* bd0   = (const float*)d_in[12];
    const float* gamma = (const float*)d_in[13];
    const float* beta  = (const float*)d_in[14];
    const float* bnm   = (const float*)d_in[15];
    const float* bnv   = (const float*)d_in[16];
    const float* al_h  = (const float*)d_in[17];
    const float* Wd1   = (const float*)d_in[18];
    const float* bd1   = (const float*)d_in[19];
    float* out = (float*)d_out;

    cudaFuncSetAttribute((const void*)fused_lstm,
                         cudaFuncAttributeMaxDynamicSharedMemorySize, FUSED_SMEM_BYTES);

    zero_flags<<<130, 256>>>();
    fused_lstm<<<128, 512, FUSED_SMEM_BYTES>>>(ids, emb, k0, rec, k12, bias);

    enc_avg<<<(int)(((size_t)TBT * UU + 255) / 256), 256>>>();
    att_scores<<<dim3(BB, TT / 16), 256>>>(Wa0, ba0, al_a, Wa1, ba1);
    softmax_pool<<<BB, 256>>>();
    head<<<BB, 256>>>(Wd0, bd0, gamma, beta, bnm, bnv, al_h, Wd1, bd1, out);
}

// round 14
// speedup vs baseline: 1.3610x; 1.3610x over previous
#include <cuda_runtime.h>
#include <cuda_bf16.h>
#include <math.h>
#include <stdint.h>

#define BB 64
#define TT 256
#define EE 300
#define UU 512
#define GG 2048
#define TBT (BB*TT)     /* 16384 rows per direction */
#define M2  (2*TBT)     /* 32768 total rows */

// ---------------- device scratch (static allocation only) ----------------
__device__ float g_z[(size_t)M2 * GG];            // [2][B][T][4U] (layer-0 input proj)
__device__ float g_hall1[(size_t)2 * TBT * UU];   // [2][B][T][U]  final-layer h (fp32)
__device__ float g_enc[(size_t)TBT * UU];         // [B][T][U]
__device__ float g_scoresP[4 * TBT];              // attention score partials
__device__ float g_pooled[BB * UU];               // [B][U]
__device__ int g_flagF[(TT + 2) * 128];           // [iter][dir*64+slice]
__device__ uint32_t g_k0f[(size_t)2 * 64 * 9728]; // prefragged k0 (bf16 B-frags)
// full-T bf16 A-fragment rings: [dir][t][mt][4096] u32
__device__ uint32_t g_ring1[(size_t)2 * TT * 4 * 4096];   // h1 (layer0 out)
__device__ uint32_t g_ring2[(size_t)2 * TT * 4 * 4096];   // h2 (layer1 out)
__device__ uint32_t g_ring3[(size_t)2 * TT * 4 * 4096];   // h3 (layer2 out)

__device__ __forceinline__ float sigf(float x) { return 1.f / (1.f + __expf(-x)); }
__device__ __forceinline__ float ssf(float x)  { return x / (1.f + fabsf(x)); }

__device__ __forceinline__ float to_tf32(float x) {
    uint32_t u; asm("cvt.rna.tf32.f32 %0, %1;" : "=r"(u) : "f"(x));
    return __uint_as_float(u);
}
__device__ __forceinline__ uint32_t fu(float x) { return __float_as_uint(x); }

__device__ __forceinline__ void stRel(int* p) {
    asm volatile("st.release.gpu.global.s32 [%0], %1;" :: "l"(p), "r"(1) : "memory");
}
__device__ __forceinline__ int acqLd(const int* p) {
    int v; asm volatile("ld.acquire.gpu.global.s32 %0, [%1];" : "=r"(v) : "l"(p) : "memory");
    return v;
}

#define MMA_TF32(d0,d1,d2,d3,a0,a1,a2,a3,b0,b1) \
    asm volatile("mma.sync.aligned.m16n8k8.row.col.f32.tf32.tf32.f32 " \
        "{%0,%1,%2,%3}, {%4,%5,%6,%7}, {%8,%9}, {%0,%1,%2,%3};" \
        : "+f"(d0), "+f"(d1), "+f"(d2), "+f"(d3) \
        : "r"(a0), "r"(a1), "r"(a2), "r"(a3), "r"(b0), "r"(b1))

#define MMA_BF16(d0,d1,d2,d3,a0,a1,a2,a3,b0,b1) \
    asm volatile("mma.sync.aligned.m16n8k16.row.col.f32.bf16.bf16.f32 " \
        "{%0,%1,%2,%3}, {%4,%5,%6,%7}, {%8,%9}, {%0,%1,%2,%3};" \
        : "+f"(d0), "+f"(d1), "+f"(d2), "+f"(d3) \
        : "r"(a0), "r"(a1), "r"(a2), "r"(a3), "r"(b0), "r"(b1))

// ============ prefrag k0: write bf16 B-fragments for the input GEMM ============
// Table layout: [d][ng (32-col group)][2432 items] mirroring stage_wfrags_k0 slots.
__global__ void prefrag_k0(const float* __restrict__ k0Base) {
    int i = blockIdx.x * 256 + threadIdx.x;
    if (i >= 2 * 64 * 2432) return;
    int d  = i / (64 * 2432);
    int r  = i % (64 * 2432);
    int ng = r / 2432;
    int j  = r % 2432;
    int cc = j >> 7;
    int nt = (j >> 5) & 3;
    int lane = j & 31;
    int gq = lane >> 2, t4 = lane & 3;
    int col = ng * 32 + nt * 8 + gq;
    const float* W = k0Base + (long)d * EE * GG;
    int k0 = cc * 16 + 2 * t4;
    __nv_bfloat16 z = __float2bfloat16_rn(0.f);
    __nv_bfloat162 b0, b1;
    b0.x = (k0     < EE) ? __float2bfloat16_rn(W[(long)k0 * GG + col])       : z;
    b0.y = (k0 + 1 < EE) ? __float2bfloat16_rn(W[(long)(k0 + 1) * GG + col]) : z;
    b1.x = (k0 + 8 < EE) ? __float2bfloat16_rn(W[(long)(k0 + 8) * GG + col]) : z;
    b1.y = (k0 + 9 < EE) ? __float2bfloat16_rn(W[(long)(k0 + 9) * GG + col]) : z;
    uint32_t* dst = g_k0f + (size_t)(d * 64 + ng) * 9728
                    + (((cc * 2 + (nt >> 1)) * 32 + lane) << 2) + (nt & 1) * 2;
    dst[0] = *(uint32_t*)&b0;
    dst[1] = *(uint32_t*)&b1;
}

// ============ input GEMM bf16: g_z = emb[ids] @ k0 + bias0 ============
// grid (M2/128, GG/32); 256 thr = 8 warps, warp wi = m-tile (16 rows).
// No SMEM, no syncs: B-frags from g_k0f (L2), A gathered from emb.
__global__ __launch_bounds__(256) void gemm_z_bf16(
    const int* __restrict__ ids, const float* __restrict__ emb,
    const float* __restrict__ biasBase)
{
    const int m0 = blockIdx.x * 128;
    const int ng = blockIdx.y;
    const int d  = m0 / TBT;
    const uint32_t* Wf = g_k0f + (size_t)(d * 64 + ng) * 9728;
    const int tid = threadIdx.x;
    const int lane = tid & 31;
    const int wi = tid >> 5;
    const int g = lane >> 2, t4 = lane & 3;

    const int m = m0 + wi * 16 + g;        // row for a0/a2; m+8 for a1/a3
    int bt = m % TBT;  int b = bt / TT,  t = bt % TT;
    int tt  = d ? (TT - 1 - t)  : t;
    int bt8 = (m + 8) % TBT; int b8 = bt8 / TT, t8 = bt8 % TT;
    int tt8 = d ? (TT - 1 - t8) : t8;
    const float* e0 = emb + (long)ids[b * TT + tt] * EE;
    const float* e1 = emb + (long)ids[b8 * TT + tt8] * EE;

    float acc[4][4];
    #pragma unroll
    for (int q = 0; q < 4; q++)
        #pragma unroll
        for (int r = 0; r < 4; r++) acc[q][r] = 0.f;

    #pragma unroll 4
    for (int cc = 0; cc < 19; cc++) {
        int kb = cc * 16 + 2 * t4;
        uint32_t a0, a1, a2, a3;
        {
            float2 v = *(const float2*)&e0[kb];
            __nv_bfloat162 p; p.x = __float2bfloat16_rn(v.x); p.y = __float2bfloat16_rn(v.y);
            a0 = *(uint32_t*)&p;
        }
        {
            float2 v = *(const float2*)&e1[kb];
            __nv_bfloat162 p; p.x = __float2bfloat16_rn(v.x); p.y = __float2bfloat16_rn(v.y);
            a1 = *(uint32_t*)&p;
        }
        if (kb + 8 < EE) {
            float2 v = *(const float2*)&e0[kb + 8];
            __nv_bfloat162 p; p.x = __float2bfloat16_rn(v.x); p.y = __float2bfloat16_rn(v.y);
            a2 = *(uint32_t*)&p;
            float2 w = *(const float2*)&e1[kb + 8];
            __nv_bfloat162 q2; q2.x = __float2bfloat16_rn(w.x); q2.y = __float2bfloat16_rn(w.y);
            a3 = *(uint32_t*)&q2;
        } else { a2 = 0; a3 = 0; }

        uint4 b0 = *(const uint4*)&Wf[((cc * 2 + 0) * 32 + lane) << 2];
        uint4 b1 = *(const uint4*)&Wf[((cc * 2 + 1) * 32 + lane) << 2];
        MMA_BF16(acc[0][0], acc[0][1], acc[0][2], acc[0][3],
                 a0, a1, a2, a3, b0.x, b0.y);
        MMA_BF16(acc[1][0], acc[1][1], acc[1][2], acc[1][3],
                 a0, a1, a2, a3, b0.z, b0.w);
        MMA_BF16(acc[2][0], acc[2][1], acc[2][2], acc[2][3],
                 a0, a1, a2, a3, b1.x, b1.y);
        MMA_BF16(acc[3][0], acc[3][1], acc[3][2], acc[3][3],
                 a0, a1, a2, a3, b1.z, b1.w);
    }

    const float* bp = biasBase + (long)d * 3 * GG + ng * 32 + 2 * t4;
    long zr0 = (long)m * GG + ng * 32 + 2 * t4;
    long zr1 = (long)(m + 8) * GG + ng * 32 + 2 * t4;
    #pragma unroll
    for (int q = 0; q < 4; q++) {
        float2 bv = *(const float2*)&bp[q * 8];
        *(float2*)&g_z[zr0 + q * 8] = make_float2(acc[q][0] + bv.x, acc[q][1] + bv.y);
        *(float2*)&g_z[zr1 + q * 8] = make_float2(acc[q][2] + bv.x, acc[q][3] + bv.y);
    }
}

// ---- stage a 512x32-gate-col weight slice as bf16 B-fragments ----
__device__ __forceinline__ void stage_wfrags32(
    uint32_t* dstW, const float* W, int u0, int tid, int nthr)
{
    for (int i = tid; i < 32 * 4 * 32; i += nthr) {
        int cc = i >> 7;
        int nt = (i >> 5) & 3;
        int lane = i & 31;
        int gq = lane >> 2, t4 = lane & 3;
        int col = nt * 8 + gq;                 // gate = col>>3, unit = col&7
        long wcol = (long)(col >> 3) * UU + u0 + (col & 7);
        int k0 = cc * 16 + 2 * t4;
        __nv_bfloat162 b0, b1;
        b0.x = __float2bfloat16_rn(W[(long)k0 * GG + wcol]);
        b0.y = __float2bfloat16_rn(W[(long)(k0 + 1) * GG + wcol]);
        b1.x = __float2bfloat16_rn(W[(long)(k0 + 8) * GG + wcol]);
        b1.y = __float2bfloat16_rn(W[(long)(k0 + 9) * GG + wcol]);
        uint32_t* dst = dstW + (((cc * 2 + (nt >> 1)) * 32 + lane) << 2) + (nt & 1) * 2;
        dst[0] = *(uint32_t*)&b0;
        dst[1] = *(uint32_t*)&b1;
    }
}

// ---- single bf16 mma stream, full 32 cols per warp ----
__device__ __forceinline__ void mma_stream4(
    float acc[4][4], const uint32_t* ring, const uint32_t* Ws, int lane)
{
    const uint4* r = (const uint4*)ring;
    uint4 buf[8];
    #pragma unroll
    for (int i = 0; i < 8; i++) buf[i] = r[i * 32 + lane];
    #pragma unroll
    for (int cc = 0; cc < 32; cc++) {
        uint4 av = buf[cc & 7];
        if (cc + 8 < 32) buf[cc & 7] = r[(cc + 8) * 32 + lane];
        uint4 b0 = *(const uint4*)&Ws[((cc * 2 + 0) * 32 + lane) << 2];
        uint4 b1 = *(const uint4*)&Ws[((cc * 2 + 1) * 32 + lane) << 2];
        MMA_BF16(acc[0][0], acc[0][1], acc[0][2], acc[0][3],
                 av.x, av.y, av.z, av.w, b0.x, b0.y);
        MMA_BF16(acc[1][0], acc[1][1], acc[1][2], acc[1][3],
                 av.x, av.y, av.z, av.w, b0.z, b0.w);
        MMA_BF16(acc[2][0], acc[2][1], acc[2][2], acc[2][3],
                 av.x, av.y, av.z, av.w, b1.x, b1.y);
        MMA_BF16(acc[3][0], acc[3][1], acc[3][2], acc[3][3],
                 av.x, av.y, av.z, av.w, b1.z, b1.w);
    }
}

// ---- dual interleaved streams ----
__device__ __forceinline__ void mma_dual(
    float acc[4][4],
    const uint32_t* ringA, const uint32_t* WsA,
    const uint32_t* ringB, const uint32_t* WsB, int lane)
{
    const uint4* rA = (const uint4*)ringA;
    const uint4* rB = (const uint4*)ringB;
    uint4 bufA[4], bufB[4];
    #pragma unroll
    for (int i = 0; i < 4; i++) { bufA[i] = rA[i * 32 + lane];
                                  bufB[i] = rB[i * 32 + lane]; }
    #pragma unroll
    for (int cc = 0; cc < 32; cc++) {
        uint4 av = bufA[cc & 3];
        uint4 bv = bufB[cc & 3];
        if (cc + 4 < 32) { bufA[cc & 3] = rA[(cc + 4) * 32 + lane];
                           bufB[cc & 3] = rB[(cc + 4) * 32 + lane]; }
        uint4 a0 = *(const uint4*)&WsA[((cc * 2 + 0) * 32 + lane) << 2];
        uint4 a1 = *(const uint4*)&WsA[((cc * 2 + 1) * 32 + lane) << 2];
        MMA_BF16(acc[0][0], acc[0][1], acc[0][2], acc[0][3],
                 av.x, av.y, av.z, av.w, a0.x, a0.y);
        MMA_BF16(acc[1][0], acc[1][1], acc[1][2], acc[1][3],
                 av.x, av.y, av.z, av.w, a0.z, a0.w);
        MMA_BF16(acc[2][0], acc[2][1], acc[2][2], acc[2][3],
                 av.x, av.y, av.z, av.w, a1.x, a1.y);
        MMA_BF16(acc[3][0], acc[3][1], acc[3][2], acc[3][3],
                 av.x, av.y, av.z, av.w, a1.z, a1.w);
        uint4 b0 = *(const uint4*)&WsB[((cc * 2 + 0) * 32 + lane) << 2];
        uint4 b1 = *(const uint4*)&WsB[((cc * 2 + 1) * 32 + lane) << 2];
        MMA_BF16(acc[0][0], acc[0][1], acc[0][2], acc[0][3],
                 bv.x, bv.y, bv.z, bv.w, b0.x, b0.y);
        MMA_BF16(acc[1][0], acc[1][1], acc[1][2], acc[1][3],
                 bv.x, bv.y, bv.z, bv.w, b0.z, b0.w);
        MMA_BF16(acc[2][0], acc[2][1], acc[2][2], acc[2][3],
                 bv.x, bv.y, bv.z, bv.w, b1.x, b1.y);
        MMA_BF16(acc[3][0], acc[3][1], acc[3][2], acc[3][3],
                 bv.x, bv.y, bv.z, bv.w, b1.z, b1.w);
    }
}

// ============ fused 3-layer bidir LSTM (R12 version, best known) ============
#define FUSED_SMEM_BYTES 163840

__global__ __launch_bounds__(384) void fused_lstm(
    const float* __restrict__ recBase, const float* __restrict__ k12Base,
    const float* __restrict__ biasBase)
{
    extern __shared__ char smraw[];
    uint32_t* Ws0  = (uint32_t*)smraw;         // rec layer0
    uint32_t* Ws1k = Ws0 + 8192;               // k12 layer1
    uint32_t* Ws1r = Ws0 + 16384;              // rec layer1
    uint32_t* Ws2k = Ws0 + 24576;              // k12 layer2
    uint32_t* Ws2r = Ws0 + 32768;              // rec layer2

    const int bx = blockIdx.x;
    const int d     = bx >> 6;
    const int slice = bx & 63;
    const int u0    = slice * 8;
    const int tid = threadIdx.x;

    stage_wfrags32(Ws0,  recBase + ((long)d * 3 + 0) * UU * GG, u0, tid, 384);
    stage_wfrags32(Ws1k, k12Base + ((long)d * 2 + 0) * UU * GG, u0, tid, 384);
    stage_wfrags32(Ws1r, recBase + ((long)d * 3 + 1) * UU * GG, u0, tid, 384);
    stage_wfrags32(Ws2k, k12Base + ((long)d * 2 + 1) * UU * GG, u0, tid, 384);
    stage_wfrags32(Ws2r, recBase + ((long)d * 3 + 2) * UU * GG, u0, tid, 384);
    __syncthreads();

    const int lane = tid & 31;
    const int wid  = tid >> 5;
    const int sg   = wid >> 2;        // stage group 0..2
    const int wi   = wid & 3;         // m-tile within group
    const int g    = lane >> 2;
    const int t4   = lane & 3;

    const int R = wi * 16 + g;        // first owned batch row (second is R+8)
    const int ringSlot = (((slice >> 1) * 32 + lane) << 2) + 2 * (slice & 1);

    float2 bg2[4];
    if (sg > 0) {
        const float* bp = biasBase + ((long)d * 3 + sg) * GG;
        #pragma unroll
        for (int q = 0; q < 4; q++)
            bg2[q] = *(const float2*)&bp[q * UU + u0 + 2 * t4];
    }

    uint32_t* ringOut = (sg == 0) ? g_ring1 : ((sg == 1) ? g_ring2 : g_ring3);

    float4 cell = make_float4(0.f, 0.f, 0.f, 0.f);

    for (int i = 0; i < TT + 2; i++) {
        const bool s0 = (i < TT);
        const bool s1 = (i >= 1 && i <= TT);
        const bool s2 = (i >= 2);
        const int t0 = i, t1 = i - 1, t2 = i - 2;
        const bool act = (sg == 0) ? s0 : ((sg == 1) ? s1 : s2);
        const int ts = (sg == 0) ? t0 : ((sg == 1) ? t1 : t2);

        float2 zA[4], zB[4];
        if (sg == 0 && s0) {
            long zb = ((long)d * TBT + (long)R * TT + t0) * GG + u0 + 2 * t4;
            long zc = zb + (long)8 * TT * GG;
            #pragma unroll
            for (int q = 0; q < 4; q++) {
                zA[q] = *(const float2*)&g_z[zb + q * UU];
                zB[q] = *(const float2*)&g_z[zc + q * UU];
            }
        }

        if (i > 0) {
            if (tid < 64) {
                const int* p = &g_flagF[(i - 1) * 128 + d * 64 + tid];
                while (acqLd(p) == 0) { }
            }
            __syncthreads();
        }

        float acc[4][4];
        #pragma unroll
        for (int q = 0; q < 4; q++)
            #pragma unroll
            for (int r = 0; r < 4; r++) acc[q][r] = 0.f;

        if (sg == 0) {
            if (s0 && t0 > 0)
                mma_stream4(acc, &g_ring1[((size_t)(d * TT + t0 - 1) * 4 + wi) * 4096],
                            Ws0, lane);
        } else if (sg == 1) {
            if (s1) {
                if (t1 > 0)
                    mma_dual(acc, &g_ring1[((size_t)(d * TT + t1) * 4 + wi) * 4096], Ws1k,
                             &g_ring2[((size_t)(d * TT + t1 - 1) * 4 + wi) * 4096], Ws1r,
                             lane);
                else
                    mma_stream4(acc, &g_ring1[((size_t)(d * TT + t1) * 4 + wi) * 4096],
                                Ws1k, lane);
            }
        } else {
            if (s2) {
                if (t2 > 0)
                    mma_dual(acc, &g_ring2[((size_t)(d * TT + t2) * 4 + wi) * 4096], Ws2k,
                             &g_ring3[((size_t)(d * TT + t2 - 1) * 4 + wi) * 4096], Ws2r,
                             lane);
                else
                    mma_stream4(acc, &g_ring2[((size_t)(d * TT + t2) * 4 + wi) * 4096],
                                Ws2k, lane);
            }
        }

        if (act) {
            float2 aA[4], aB[4];
            if (sg == 0) {
                #pragma unroll
                for (int q = 0; q < 4; q++) { aA[q] = zA[q]; aB[q] = zB[q]; }
            } else {
                #pragma unroll
                for (int q = 0; q < 4; q++) { aA[q] = bg2[q]; aB[q] = bg2[q]; }
            }
            float ci0 = acc[0][0] + aA[0].x, ci1 = acc[0][1] + aA[0].y;
            float cf0 = acc[1][0] + aA[1].x, cf1 = acc[1][1] + aA[1].y;
            float cg0 = acc[2][0] + aA[2].x, cg1 = acc[2][1] + aA[2].y;
            float co0 = acc[3][0] + aA[3].x, co1 = acc[3][1] + aA[3].y;
            float ci2 = acc[0][2] + aB[0].x, ci3 = acc[0][3] + aB[0].y;
            float cf2 = acc[1][2] + aB[1].x, cf3 = acc[1][3] + aB[1].y;
            float cg2v = acc[2][2] + aB[2].x, cg3 = acc[2][3] + aB[2].y;
            float co2 = acc[3][2] + aB[3].x, co3 = acc[3][3] + aB[3].y;

            cell.x = sigf(cf0) * cell.x + sigf(ci0) * ssf(cg0);
            cell.y = sigf(cf1) * cell.y + sigf(ci1) * ssf(cg1);
            cell.z = sigf(cf2) * cell.z + sigf(ci2) * ssf(cg2v);
            cell.w = sigf(cf3) * cell.w + sigf(ci3) * ssf(cg3);
            float h0 = sigf(co0) * ssf(cell.x);
            float h1 = sigf(co1) * ssf(cell.y);
            float h2 = sigf(co2) * ssf(cell.z);
            float h3 = sigf(co3) * ssf(cell.w);

            if (sg == 2) {
                long hb = ((long)d * TBT + (long)R * TT + ts) * UU + u0 + 2 * t4;
                *(float2*)&g_hall1[hb] = make_float2(h0, h1);
                *(float2*)&g_hall1[hb + (long)8 * TT * UU] = make_float2(h2, h3);
            }
            __nv_bfloat162 p0, p1;
            p0.x = __float2bfloat16_rn(h0); p0.y = __float2bfloat16_rn(h1);
            p1.x = __float2bfloat16_rn(h2); p1.y = __float2bfloat16_rn(h3);
            uint2 pk = make_uint2(*(uint32_t*)&p0, *(uint32_t*)&p1);
            *(uint2*)&ringOut[((size_t)(d * TT + ts) * 4 + wi) * 4096 + ringSlot] = pk;
        }

        __syncthreads();
        if (tid == 0) stRel(&g_flagF[i * 128 + d * 64 + slice]);
    }
}

__global__ void zero_flags() {
    int i = blockIdx.x * 256 + threadIdx.x;
    if (i < (TT + 2) * 128) g_flagF[i] = 0;
}

__global__ void enc_avg() {
    size_t i = (size_t)blockIdx.x * blockDim.x + threadIdx.x;
    if (i < (size_t)TBT * UU)
        g_enc[i] = 0.5f * (g_hall1[i] + g_hall1[(size_t)TBT * UU + i]);
}

// ============ attention scores via tf32 mma ============
// grid (16384/128, 256/64); computes partial scores per 64-col group into g_scoresP.
__global__ __launch_bounds__(256) void att_mma(
    const float* __restrict__ Wa0, const float* __restrict__ ba0,
    const float* __restrict__ alpha_a, const float* __restrict__ Wa1)
{
    __shared__ float As[128 * 36];
    __shared__ float Bs[32 * 72];
    __shared__ float sred[2][128];

    const int m0 = blockIdx.x * 128;
    const int n0 = blockIdx.y * 64;
    const int tid = threadIdx.x;

    const int w = tid >> 5, lane = tid & 31;
    const int g = lane >> 2, t4 = lane & 3;
    const int mw = (w >> 1) * 32;
    const int nw = (w & 1) * 32;

    float acc[2][4][4];
    #pragma unroll
    for (int a = 0; a < 2; a++)
        #pragma unroll
        for (int b = 0; b < 4; b++)
            #pragma unroll
            for (int c = 0; c < 4; c++) acc[a][b][c] = 0.f;

    float4 aP[4], bP[2];
    const float* Abase = g_enc + (size_t)m0 * UU;

    auto ldA = [&](int kb) {
        #pragma unroll
        for (int i = 0; i < 4; i++) {
            int idx = tid + i * 256;
            int row = idx >> 3, c4 = idx & 7;
            aP[i] = *(const float4*)(Abase + (size_t)row * UU + kb + c4 * 4);
        }
    };
    auto ldB = [&](int kb) {
        #pragma unroll
        for (int i = 0; i < 2; i++) {
            int idx = tid + i * 256;
            int kr = idx >> 4, c4 = idx & 15;
            bP[i] = *(const float4*)(Wa0 + (size_t)(kb + kr) * 256 + n0 + c4 * 4);
        }
    };

    ldA(0); ldB(0);

    for (int c = 0; c < 16; c++) {
        __syncthreads();
        #pragma unroll
        for (int i = 0; i < 4; i++) {
            int idx = tid + i * 256;
            int row = idx >> 3, c4 = idx & 7;
            float4 v = aP[i];
            *(float4*)&As[row * 36 + c4 * 4] =
                make_float4(to_tf32(v.x), to_tf32(v.y), to_tf32(v.z), to_tf32(v.w));
        }
        #pragma unroll
        for (int i = 0; i < 2; i++) {
            int idx = tid + i * 256;
            int kr = idx >> 4, c4 = idx & 15;
            float4 v = bP[i];
            *(float4*)&Bs[kr * 72 + c4 * 4] =
                make_float4(to_tf32(v.x), to_tf32(v.y), to_tf32(v.z), to_tf32(v.w));
        }
        __syncthreads();
        if (c + 1 < 16) { ldA((c + 1) * 32); ldB((c + 1) * 32); }

        #pragma unroll
        for (int kk = 0; kk < 32; kk += 8) {
            uint32_t a[2][4];
            #pragma unroll
            for (int mt = 0; mt < 2; mt++) {
                int rb = mw + mt * 16;
                a[mt][0] = fu(As[(rb + g)     * 36 + kk + t4]);
                a[mt][1] = fu(As[(rb + 8 + g) * 36 + kk + t4]);
                a[mt][2] = fu(As[(rb + g)     * 36 + kk + t4 + 4]);
                a[mt][3] = fu(As[(rb + 8 + g) * 36 + kk + t4 + 4]);
            }
            #pragma unroll
            for (int nt = 0; nt < 4; nt++) {
                uint32_t b0 = fu(Bs[(kk + t4)     * 72 + nw + nt * 8 + g]);
                uint32_t b1 = fu(Bs[(kk + t4 + 4) * 72 + nw + nt * 8 + g]);
                MMA_TF32(acc[0][nt][0], acc[0][nt][1], acc[0][nt][2], acc[0][nt][3],
                         a[0][0], a[0][1], a[0][2], a[0][3], b0, b1);
                MMA_TF32(acc[1][nt][0], acc[1][nt][1], acc[1][nt][2], acc[1][nt][3],
                         a[1][0], a[1][1], a[1][2], a[1][3], b0, b1);
            }
        }
    }

    // epilogue: prelu + Wa1-dot partials for 4 owned rows
    float pr[4] = {0.f, 0.f, 0.f, 0.f};   // [mt*2 + half]
    #pragma unroll
    for (int nt = 0; nt < 4; nt++) {
        int c0 = n0 + nw + nt * 8 + 2 * t4;
        float b0 = ba0[c0],     b1 = ba0[c0 + 1];
        float al0 = alpha_a[c0], al1 = alpha_a[c0 + 1];
        float w0 = Wa1[c0],     w1 = Wa1[c0 + 1];
        #pragma unroll
        for (int mt = 0; mt < 2; mt++) {
            float v0 = acc[mt][nt][0] + b0;
            float v1 = acc[mt][nt][1] + b1;
            float v2 = acc[mt][nt][2] + b0;
            float v3 = acc[mt][nt][3] + b1;
            v0 = (v0 >= 0.f) ? v0 : al0 * v0;
            v1 = (v1 >= 0.f) ? v1 : al1 * v1;
            v2 = (v2 >= 0.f) ? v2 : al0 * v2;
            v3 = (v3 >= 0.f) ? v3 : al1 * v3;
            pr[mt * 2]     += v0 * w0 + v1 * w1;
            pr[mt * 2 + 1] += v2 * w0 + v3 * w1;
        }
    }
    #pragma unroll
    for (int q = 0; q < 4; q++) {
        pr[q] += __shfl_xor_sync(0xffffffff, pr[q], 1);
        pr[q] += __shfl_xor_sync(0xffffffff, pr[q], 2);
    }
    if (t4 == 0) {
        #pragma unroll
        for (int mt = 0; mt < 2; mt++) {
            sred[nw >> 5][mw + mt * 16 + g]     = pr[mt * 2];
            sred[nw >> 5][mw + mt * 16 + g + 8] = pr[mt * 2 + 1];
        }
    }
    __syncthreads();
    if (tid < 128)
        g_scoresP[blockIdx.y * TBT + m0 + tid] = sred[0][tid] + sred[1][tid];
}

// ---------------- softmax over T + weighted pooling ----------------
__global__ __launch_bounds__(256) void softmax_pool(const float* __restrict__ ba1) {
    const int b = blockIdx.x;
    const int tid = threadIdx.x;
    __shared__ float ws[256];
    __shared__ float red[256];

    int idx = b * TT + tid;
    float s = g_scoresP[idx] + g_scoresP[TBT + idx]
            + g_scoresP[2 * TBT + idx] + g_scoresP[3 * TBT + idx] + ba1[0];
    red[tid] = s; __syncthreads();
    for (int st = 128; st > 0; st >>= 1) {
        if (tid < st) red[tid] = fmaxf(red[tid], red[tid + st]);
        __syncthreads();
    }
    float mx = red[0]; __syncthreads();
    float e = expf(s - mx);
    red[tid] = e; __syncthreads();
    for (int st = 128; st > 0; st >>= 1) {
        if (tid < st) red[tid] += red[tid + st];
        __syncthreads();
    }
    float sum = red[0]; __syncthreads();
    ws[tid] = e / sum;
    __syncthreads();

    for (int u = tid; u < UU; u += 256) {
        float acc = 0.f;
        for (int t = 0; t < TT; t++)
            acc += g_enc[((size_t)b * TT + t) * UU + u] * ws[t];
        g_pooled[b * UU + u] = acc;
    }
}

// ---------------- classification head ----------------
__global__ __launch_bounds__(256) void head(
    const float* __restrict__ Wd0, const float* __restrict__ bd0,
    const float* __restrict__ gamma, const float* __restrict__ beta,
    const float* __restrict__ bnm, const float* __restrict__ bnv,
    const float* __restrict__ alpha_h, const float* __restrict__ Wd1,
    const float* __restrict__ bd1, float* __restrict__ out)
{
    const int b = blockIdx.x, j = threadIdx.x;
    __shared__ float ps[512];
    __shared__ float hs[256];
    __shared__ float lgs[7];

    for (int u = j; u < 512; u += 256) ps[u] = g_pooled[b * UU + u];
    __syncthreads();

    float h = bd0[j];
    for (int u = 0; u < 512; u++) h += ps[u] * Wd0[u * 256 + j];
    h = (h - bnm[j]) * rsqrtf(bnv[j] + 1e-3f) * gamma[j] + beta[j];
    h = (h >= 0.f) ? h : alpha_h[j] * h;
    hs[j] = h;
    __syncthreads();

    if (j < 7) {
        float lg = bd1[j];
        for (int k = 0; k < 256; k++) lg += hs[k] * Wd1[k * 7 + j];
        lgs[j] = lg;
    }
    __syncthreads();
    if (j == 0) {
        float mx = lgs[0];
        for (int l = 1; l < 7; l++) mx = fmaxf(mx, lgs[l]);
        float sum = 0.f, e[7];
        for (int l = 0; l < 7; l++) { e[l] = expf(lgs[l] - mx); sum += e[l]; }
        for (int l = 0; l < 7; l++) out[b * 7 + l] = e[l] / sum;
    }
}

// ---------------- driver ----------------
extern "C" void kernel_launch(void* const* d_in, const int* in_sizes, int n_in,
                              void* d_out, int out_size)
{
    const int*   ids   = (const int*)  d_in[0];
    const float* emb   = (const float*)d_in[1];
    const float* k0    = (const float*)d_in[2];
    const float* k12   = (const float*)d_in[3];
    const float* rec   = (const float*)d_in[4];
    const float* bias  = (const float*)d_in[5];
    const float* Wa0   = (const float*)d_in[6];
    const float* ba0   = (const float*)d_in[7];
    const float* al_a  = (const float*)d_in[8];
    const float* Wa1   = (const float*)d_in[9];
    const float* ba1   = (const float*)d_in[10];
    const float* Wd0   = (const float*)d_in[11];
    const float* bd0   = (const float*)d_in[12];
    const float* gamma = (const float*)d_in[13];
    const float* beta  = (const float*)d_in[14];
    const float* bnm   = (const float*)d_in[15];
    const float* bnv   = (const float*)d_in[16];
    const float* al_h  = (const float*)d_in[17];
    const float* Wd1   = (const float*)d_in[18];
    const float* bd1   = (const float*)d_in[19];
    float* out = (float*)d_out;

    cudaFuncSetAttribute((const void*)fused_lstm,
                         cudaFuncAttributeMaxDynamicSharedMemorySize, FUSED_SMEM_BYTES);

    prefrag_k0<<<1216, 256>>>(k0);
    zero_flags<<<130, 256>>>();
    gemm_z_bf16<<<dim3(M2 / 128, 64), 256>>>(ids, emb, bias);
    fused_lstm<<<128, 384, FUSED_SMEM_BYTES>>>(rec, k12, bias);

    enc_avg<<<(int)(((size_t)TBT * UU + 255) / 256), 256>>>();
    att_mma<<<dim3(TBT / 128, 4), 256>>>(Wa0, ba0, al_a, Wa1);
    softmax_pool<<<BB, 256>>>(ba1);
    head<<<BB, 256>>>(Wd0, bd0, gamma, beta, bnm, bnv, al_h, Wd1, bd1, out);
}